// round 2
// baseline (speedup 1.0000x reference)
#include <cuda_runtime.h>
#include <math.h>

// Problem constants
#define BB 8
#define CC 128
#define HH 96
#define WW 96
#define PP (HH*WW)       // 9216
#define NG 16            // groups
#define CPG 8            // channels per group

// ---------------- scratch (device globals; no allocs allowed) ----------------
__device__ float g_avg [BB*PP];            // mean over channels
__device__ float g_invn[BB*PP];            // 1/max(||x||_C, 1e-12)
__device__ float g_df  [BB*PP];            // |laplacian(avg)|
__device__ unsigned g_mm[2*BB];            // per-batch min/max bits of df
__device__ float g_gs  [BB*NG];            // group sums
__device__ float g_gss [BB*NG];            // group sumsq
__device__ float g_gnm [BB*NG];            // group mean
__device__ float g_gni [BB*NG];            // group invstd
__device__ float g_enh [BB*CC*PP];         // enhanced (out + groupnorm)
__device__ float g_h   [BB*256*PP];        // hidden activations

__device__ __forceinline__ int refl(int i) {
    // jnp.pad 'reflect': -1 -> 1, H -> H-2
    return i < 0 ? -i : (i >= HH ? 2*HH - 2 - i : i);
}

// ---------------- K0: reset accumulators ----------------
__global__ void k_init() {
    int t = threadIdx.x;
    if (t < BB*NG) { g_gs[t] = 0.f; g_gss[t] = 0.f; }
    if (t < BB) { g_mm[2*t] = 0x7F800000u; g_mm[2*t+1] = 0u; }
}

// ---------------- K1: per-pixel avg & inv-norm, per-(b,g) sums ----------------
__global__ void k_stats(const float* __restrict__ x) {
    int tid = threadIdx.x;
    int idx = blockIdx.x * 256 + tid;        // (b,p)
    int b = idx / PP;
    const float* xb = x + (size_t)b * CC * PP + (idx - b*PP);
    int lane = tid & 31;

    __shared__ float s_gs[NG], s_gss[NG];
    if (tid < NG) { s_gs[tid] = 0.f; s_gss[tid] = 0.f; }
    __syncthreads();

    float sum = 0.f, ssq = 0.f;
    #pragma unroll
    for (int g = 0; g < NG; g++) {
        float gs = 0.f, gss = 0.f;
        #pragma unroll
        for (int cc = 0; cc < CPG; cc++) {
            float v = xb[(size_t)(g*CPG + cc) * PP];
            gs += v; gss += v*v;
        }
        sum += gs; ssq += gss;
        #pragma unroll
        for (int off = 16; off; off >>= 1) {
            gs  += __shfl_xor_sync(0xffffffffu, gs,  off);
            gss += __shfl_xor_sync(0xffffffffu, gss, off);
        }
        if (lane == 0) { atomicAdd(&s_gs[g], gs); atomicAdd(&s_gss[g], gss); }
    }
    __syncthreads();
    if (tid < NG) {
        atomicAdd(&g_gs [b*NG + tid], s_gs [tid]);
        atomicAdd(&g_gss[b*NG + tid], s_gss[tid]);
    }
    g_avg [idx] = sum * (1.f/128.f);
    g_invn[idx] = 1.f / fmaxf(sqrtf(ssq), 1e-12f);
}

// ---------------- K2: laplacian of avg (zero pad), per-batch min/max ----------------
__global__ void k_df() {
    int tid = threadIdx.x;
    int idx = blockIdx.x * 256 + tid;
    int b = idx / PP;
    int p = idx - b*PP;
    int y = p / WW, xq = p - y*WW;
    float c = g_avg[idx];
    float up = (y > 0)      ? g_avg[idx - WW] : 0.f;
    float dn = (y < HH-1)   ? g_avg[idx + WW] : 0.f;
    float lf = (xq > 0)     ? g_avg[idx - 1]  : 0.f;
    float rt = (xq < WW-1)  ? g_avg[idx + 1]  : 0.f;
    float df = fabsf(4.f*c - up - dn - lf - rt);
    g_df[idx] = df;

    __shared__ float smn[256], smx[256];
    smn[tid] = df; smx[tid] = df;
    __syncthreads();
    for (int s = 128; s; s >>= 1) {
        if (tid < s) {
            smn[tid] = fminf(smn[tid], smn[tid+s]);
            smx[tid] = fmaxf(smx[tid], smx[tid+s]);
        }
        __syncthreads();
    }
    if (tid == 0) {
        atomicMin(&g_mm[2*b],   __float_as_uint(smn[0]));
        atomicMax(&g_mm[2*b+1], __float_as_uint(smx[0]));
    }
}

// ---------------- K3: finalize GN stats ----------------
__global__ void k_gn() {
    int i = threadIdx.x;
    if (i < BB*NG) {
        const float N = (float)(CPG * PP);
        float mean = g_gs[i] / N;
        float var = g_gss[i] / N - mean*mean;
        g_gnm[i] = mean;
        g_gni[i] = rsqrtf(var + 1e-5f);
    }
}

// ---------------- K4: IPG core (sims, top-k softmax, weighted sum + GN) -------
#define TW 32
#define TH 8
#define ROWW 34          // TW+2
#define TILE (10*ROWW)   // 340

#define CE(a_,b_) do { \
    if ((sv[b_] > sv[a_]) || (sv[b_] == sv[a_] && si[b_] < si[a_])) { \
        float t_ = sv[a_]; sv[a_] = sv[b_]; sv[b_] = t_; \
        int u_ = si[a_]; si[a_] = si[b_]; si[b_] = u_; } \
} while (0)

__global__ void __launch_bounds__(256) k_main(const float* __restrict__ x,
                                              const float* __restrict__ gnw,
                                              const float* __restrict__ gnb) {
    int b = blockIdx.z;
    int x0 = blockIdx.x * TW, y0 = blockIdx.y * TH;
    int tx = threadIdx.x, ty = threadIdx.y;
    int tid = ty * TW + tx;

    __shared__ float s_inv[TILE];
    __shared__ float s_t[8][TILE];
    __shared__ float s_mean[NG], s_istd[NG];

    if (tid < NG) { s_mean[tid] = g_gnm[b*NG+tid]; s_istd[tid] = g_gni[b*NG+tid]; }
    for (int i = tid; i < TILE; i += 256) {
        int yy = i / ROWW, xx = i - yy*ROWW;
        int gy = refl(y0 + yy - 1), gx = refl(x0 + xx - 1);
        s_inv[i] = g_invn[b*PP + gy*WW + gx];
    }
    __syncthreads();

    float dots[9];
    #pragma unroll
    for (int j = 0; j < 9; j++) dots[j] = 0.f;

    // pass 1: dot products
    for (int c0 = 0; c0 < CC; c0 += 8) {
        for (int i = tid; i < 8*TILE; i += 256) {
            int c = i / TILE, r = i - c*TILE;
            int yy = r / ROWW, xx = r - yy*ROWW;
            int gy = refl(y0 + yy - 1), gx = refl(x0 + xx - 1);
            s_t[c][r] = x[(size_t)((b*CC) + c0 + c) * PP + gy*WW + gx];
        }
        __syncthreads();
        #pragma unroll
        for (int cc = 0; cc < 8; cc++) {
            const float* t = s_t[cc];
            float v = t[(ty+1)*ROWW + tx + 1];
            #pragma unroll
            for (int dy = 0; dy < 3; dy++)
                #pragma unroll
                for (int dx = 0; dx < 3; dx++)
                    dots[dy*3+dx] += v * t[(ty+dy)*ROWW + tx + dx];
        }
        __syncthreads();
    }

    float invc = s_inv[(ty+1)*ROWW + tx + 1];
    float sims[9];
    #pragma unroll
    for (int j = 0; j < 9; j++) {
        int dy = j / 3, dx = j - dy*3;
        sims[j] = dots[j] * invc * s_inv[(ty+dy)*ROWW + tx + dx];
    }

    // connection count k from DF
    int p = (y0 + ty) * WW + x0 + tx;
    float df = g_df[b*PP + p];
    float mn = __uint_as_float(g_mm[2*b]);
    float mx = __uint_as_float(g_mm[2*b+1]);
    float dn = (df - mn) / (mx - mn + 1e-8f);
    int k = 1 + (int)rintf(dn * 7.f);           // [1,8], round-half-even matches jnp
    if (k < 1) k = 1; if (k > 8) k = 8;

    // stable descending sort of (sim, idx) via 9-element network (registers only)
    float sv[9]; int si[9];
    #pragma unroll
    for (int j = 0; j < 9; j++) { sv[j] = sims[j]; si[j] = j; }
    CE(0,3); CE(1,7); CE(2,5); CE(4,8);
    CE(0,7); CE(2,4); CE(3,8); CE(5,6);
    CE(0,2); CE(1,3); CE(4,5); CE(7,8);
    CE(1,4); CE(3,6); CE(5,7);
    CE(0,1); CE(2,4); CE(3,5); CE(6,8);
    CE(2,3); CE(4,5); CE(6,7);
    CE(1,2); CE(3,4); CE(5,6);

    // (k-1)-th element = selection threshold
    float ts = sv[0]; int tix = si[0];
    #pragma unroll
    for (int r = 0; r < 9; r++) { if (r == k-1) { ts = sv[r]; tix = si[r]; } }

    float wj[9]; float ws = 0.f;
    #pragma unroll
    for (int j = 0; j < 9; j++) {
        bool sel = (sims[j] > ts) || (sims[j] == ts && j <= tix);
        wj[j] = sel ? expf(sims[j]) : 0.f;
        ws += wj[j];
    }
    float iws = 1.f / ws;
    #pragma unroll
    for (int j = 0; j < 9; j++) wj[j] *= iws;

    // pass 2: weighted neighbor sum + groupnorm -> enhanced
    for (int c0 = 0; c0 < CC; c0 += 8) {
        for (int i = tid; i < 8*TILE; i += 256) {
            int c = i / TILE, r = i - c*TILE;
            int yy = r / ROWW, xx = r - yy*ROWW;
            int gy = refl(y0 + yy - 1), gx = refl(x0 + xx - 1);
            s_t[c][r] = x[(size_t)((b*CC) + c0 + c) * PP + gy*WW + gx];
        }
        __syncthreads();
        int g = c0 >> 3;
        float gm = s_mean[g], gi = s_istd[g];
        #pragma unroll
        for (int cc = 0; cc < 8; cc++) {
            const float* t = s_t[cc];
            float acc = 0.f;
            #pragma unroll
            for (int dy = 0; dy < 3; dy++)
                #pragma unroll
                for (int dx = 0; dx < 3; dx++)
                    acc += wj[dy*3+dx] * t[(ty+dy)*ROWW + tx + dx];
            float ctr = t[(ty+1)*ROWW + tx + 1];
            int c = c0 + cc;
            float gn = (ctr - gm) * gi * gnw[c] + gnb[c];
            g_enh[(size_t)(b*CC + c) * PP + p] = acc + gn;
        }
        __syncthreads();
    }
}

// ---------------- K5/K6: FFN GEMMs (register-tiled fp32) ----------------
// G1: H = relu(W1[256x128] @ E[128xP] + b1), per batch
__global__ void __launch_bounds__(256) k_ffn1(const float* __restrict__ w1,
                                              const float* __restrict__ b1) {
    int bm = blockIdx.x, bn = blockIdx.y, b = blockIdx.z;
    __shared__ float a_s[16][68];
    __shared__ float b_s[16][128];
    const float* E = g_enh + (size_t)b * CC * PP;

    float acc[8][4];
    #pragma unroll
    for (int i = 0; i < 8; i++)
        #pragma unroll
        for (int j = 0; j < 4; j++) acc[i][j] = 0.f;

    int tm = (threadIdx.x >> 5) * 8;
    int tn = (threadIdx.x & 31) * 4;

    for (int k0 = 0; k0 < 128; k0 += 16) {
        for (int i = threadIdx.x; i < 1024; i += 256) {
            int m = i >> 4, k = i & 15;
            a_s[k][m] = w1[(bm*64 + m) * 128 + k0 + k];
        }
        for (int i = threadIdx.x; i < 512; i += 256) {
            int k = i >> 5, n4 = (i & 31) * 4;
            *(float4*)&b_s[k][n4] = *(const float4*)&E[(size_t)(k0+k)*PP + bn*128 + n4];
        }
        __syncthreads();
        #pragma unroll
        for (int kk = 0; kk < 16; kk++) {
            float a[8], bb[4];
            *(float4*)(a)   = *(float4*)&a_s[kk][tm];
            *(float4*)(a+4) = *(float4*)&a_s[kk][tm+4];
            *(float4*)(bb)  = *(float4*)&b_s[kk][tn];
            #pragma unroll
            for (int i = 0; i < 8; i++)
                #pragma unroll
                for (int j = 0; j < 4; j++)
                    acc[i][j] += a[i] * bb[j];
        }
        __syncthreads();
    }
    #pragma unroll
    for (int i = 0; i < 8; i++) {
        int m = bm*64 + tm + i;
        float bias = b1[m];
        float4 o;
        o.x = fmaxf(acc[i][0] + bias, 0.f);
        o.y = fmaxf(acc[i][1] + bias, 0.f);
        o.z = fmaxf(acc[i][2] + bias, 0.f);
        o.w = fmaxf(acc[i][3] + bias, 0.f);
        *(float4*)&g_h[(size_t)(b*256 + m) * PP + bn*128 + tn] = o;
    }
}

// G2: out = E + (W2[128x256] @ H[256xP] + b2)
__global__ void __launch_bounds__(256) k_ffn2(const float* __restrict__ w2,
                                              const float* __restrict__ b2,
                                              float* __restrict__ out) {
    int bm = blockIdx.x, bn = blockIdx.y, b = blockIdx.z;
    __shared__ float a_s[16][68];
    __shared__ float b_s[16][128];
    const float* Hb = g_h + (size_t)b * 256 * PP;

    float acc[8][4];
    #pragma unroll
    for (int i = 0; i < 8; i++)
        #pragma unroll
        for (int j = 0; j < 4; j++) acc[i][j] = 0.f;

    int tm = (threadIdx.x >> 5) * 8;
    int tn = (threadIdx.x & 31) * 4;

    for (int k0 = 0; k0 < 256; k0 += 16) {
        for (int i = threadIdx.x; i < 1024; i += 256) {
            int m = i >> 4, k = i & 15;
            a_s[k][m] = w2[(bm*64 + m) * 256 + k0 + k];
        }
        for (int i = threadIdx.x; i < 512; i += 256) {
            int k = i >> 5, n4 = (i & 31) * 4;
            *(float4*)&b_s[k][n4] = *(const float4*)&Hb[(size_t)(k0+k)*PP + bn*128 + n4];
        }
        __syncthreads();
        #pragma unroll
        for (int kk = 0; kk < 16; kk++) {
            float a[8], bb[4];
            *(float4*)(a)   = *(float4*)&a_s[kk][tm];
            *(float4*)(a+4) = *(float4*)&a_s[kk][tm+4];
            *(float4*)(bb)  = *(float4*)&b_s[kk][tn];
            #pragma unroll
            for (int i = 0; i < 8; i++)
                #pragma unroll
                for (int j = 0; j < 4; j++)
                    acc[i][j] += a[i] * bb[j];
        }
        __syncthreads();
    }
    #pragma unroll
    for (int i = 0; i < 8; i++) {
        int m = bm*64 + tm + i;
        float bias = b2[m];
        size_t row = (size_t)(b*CC + m) * PP + bn*128 + tn;
        float4 e = *(float4*)&g_enh[row];
        float4 o;
        o.x = acc[i][0] + bias + e.x;
        o.y = acc[i][1] + bias + e.y;
        o.z = acc[i][2] + bias + e.z;
        o.w = acc[i][3] + bias + e.w;
        *(float4*)&out[row] = o;
    }
}

// ---------------- launch ----------------
extern "C" void kernel_launch(void* const* d_in, const int* in_sizes, int n_in,
                              void* d_out, int out_size) {
    const float* x   = (const float*)d_in[0];
    const float* gnw = (const float*)d_in[1];
    const float* gnb = (const float*)d_in[2];
    const float* w1  = (const float*)d_in[3];
    const float* b1  = (const float*)d_in[4];
    const float* w2  = (const float*)d_in[5];
    const float* b2  = (const float*)d_in[6];
    float* out = (float*)d_out;

    k_init <<<1, 256>>>();
    k_stats<<<BB*PP/256, 256>>>(x);
    k_df   <<<BB*PP/256, 256>>>();
    k_gn   <<<1, 128>>>();
    k_main <<<dim3(WW/TW, HH/TH, BB), dim3(TW, TH)>>>(x, gnw, gnb);
    k_ffn1 <<<dim3(4, PP/128, BB), 256>>>(w1, b1);
    k_ffn2 <<<dim3(2, PP/128, BB), 256>>>(w2, b2, out);
}

// round 3
// speedup vs baseline: 1.8804x; 1.8804x over previous
#include <cuda_runtime.h>
#include <math.h>

// Problem constants
#define BB 8
#define CC 128
#define HH 96
#define WW 96
#define PP (HH*WW)       // 9216
#define NG 16            // groups
#define CPG 8            // channels per group

// ---------------- scratch (device globals; no allocs allowed) ----------------
__device__ float g_avg [BB*PP];            // mean over channels
__device__ float g_invn[BB*PP];            // 1/max(||x||_C, 1e-12)
__device__ float g_df  [BB*PP];            // |laplacian(avg)|
__device__ unsigned g_mm[2*BB];            // per-batch min/max bits of df
__device__ float g_gs  [BB*NG];            // group sums
__device__ float g_gss [BB*NG];            // group sumsq
__device__ float g_gnm [BB*NG];            // group mean
__device__ float g_gni [BB*NG];            // group invstd
__device__ float g_enh [BB*CC*PP];         // enhanced (out + groupnorm)
__device__ float g_h   [BB*256*PP];        // hidden activations

__device__ __forceinline__ int refl(int i) {
    return i < 0 ? -i : (i >= HH ? 2*HH - 2 - i : i);
}

__device__ __forceinline__ unsigned f2tf(float f) {
    unsigned r;
    asm("cvt.rna.tf32.f32 %0, %1;" : "=r"(r) : "f"(f));
    return r;
}

// ---------------- K0: reset accumulators ----------------
__global__ void k_init() {
    int t = threadIdx.x;
    if (t < BB*NG) { g_gs[t] = 0.f; g_gss[t] = 0.f; }
    if (t < BB) { g_mm[2*t] = 0x7F800000u; g_mm[2*t+1] = 0u; }
}

// ---------------- K1: per-pixel avg & inv-norm, per-(b,g) sums ----------------
__global__ void k_stats(const float* __restrict__ x) {
    int tid = threadIdx.x;
    int idx = blockIdx.x * 256 + tid;        // (b,p)
    int b = idx / PP;
    const float* xb = x + (size_t)b * CC * PP + (idx - b*PP);
    int lane = tid & 31;

    __shared__ float s_gs[NG], s_gss[NG];
    if (tid < NG) { s_gs[tid] = 0.f; s_gss[tid] = 0.f; }
    __syncthreads();

    float sum = 0.f, ssq = 0.f;
    #pragma unroll
    for (int g = 0; g < NG; g++) {
        float gs = 0.f, gss = 0.f;
        #pragma unroll
        for (int cc = 0; cc < CPG; cc++) {
            float v = xb[(size_t)(g*CPG + cc) * PP];
            gs += v; gss += v*v;
        }
        sum += gs; ssq += gss;
        #pragma unroll
        for (int off = 16; off; off >>= 1) {
            gs  += __shfl_xor_sync(0xffffffffu, gs,  off);
            gss += __shfl_xor_sync(0xffffffffu, gss, off);
        }
        if (lane == 0) { atomicAdd(&s_gs[g], gs); atomicAdd(&s_gss[g], gss); }
    }
    __syncthreads();
    if (tid < NG) {
        atomicAdd(&g_gs [b*NG + tid], s_gs [tid]);
        atomicAdd(&g_gss[b*NG + tid], s_gss[tid]);
    }
    g_avg [idx] = sum * (1.f/128.f);
    g_invn[idx] = 1.f / fmaxf(sqrtf(ssq), 1e-12f);
}

// ---------------- K2: laplacian of avg (zero pad), per-batch min/max ----------------
__global__ void k_df() {
    int tid = threadIdx.x;
    int idx = blockIdx.x * 256 + tid;
    int b = idx / PP;
    int p = idx - b*PP;
    int y = p / WW, xq = p - y*WW;
    float c = g_avg[idx];
    float up = (y > 0)      ? g_avg[idx - WW] : 0.f;
    float dn = (y < HH-1)   ? g_avg[idx + WW] : 0.f;
    float lf = (xq > 0)     ? g_avg[idx - 1]  : 0.f;
    float rt = (xq < WW-1)  ? g_avg[idx + 1]  : 0.f;
    float df = fabsf(4.f*c - up - dn - lf - rt);
    g_df[idx] = df;

    __shared__ float smn[256], smx[256];
    smn[tid] = df; smx[tid] = df;
    __syncthreads();
    for (int s = 128; s; s >>= 1) {
        if (tid < s) {
            smn[tid] = fminf(smn[tid], smn[tid+s]);
            smx[tid] = fmaxf(smx[tid], smx[tid+s]);
        }
        __syncthreads();
    }
    if (tid == 0) {
        atomicMin(&g_mm[2*b],   __float_as_uint(smn[0]));
        atomicMax(&g_mm[2*b+1], __float_as_uint(smx[0]));
    }
}

// ---------------- K3: finalize GN stats ----------------
__global__ void k_gn() {
    int i = threadIdx.x;
    if (i < BB*NG) {
        const float N = (float)(CPG * PP);
        float mean = g_gs[i] / N;
        float var = g_gss[i] / N - mean*mean;
        g_gnm[i] = mean;
        g_gni[i] = rsqrtf(var + 1e-5f);
    }
}

// ---------------- K4: IPG core (sims, top-k softmax, weighted sum + GN) -------
#define TW 32
#define TH 8
#define ROWW 34          // TW+2
#define TILE (10*ROWW)   // 340

#define CE(a_,b_) do { \
    if ((sv[b_] > sv[a_]) || (sv[b_] == sv[a_] && si[b_] < si[a_])) { \
        float t_ = sv[a_]; sv[a_] = sv[b_]; sv[b_] = t_; \
        int u_ = si[a_]; si[a_] = si[b_]; si[b_] = u_; } \
} while (0)

__global__ void __launch_bounds__(256) k_main(const float* __restrict__ x,
                                              const float* __restrict__ gnw,
                                              const float* __restrict__ gnb) {
    int b = blockIdx.z;
    int x0 = blockIdx.x * TW, y0 = blockIdx.y * TH;
    int tx = threadIdx.x, ty = threadIdx.y;
    int tid = ty * TW + tx;

    __shared__ float s_inv[TILE];
    __shared__ float s_t[8][TILE];
    __shared__ float s_mean[NG], s_istd[NG];

    if (tid < NG) { s_mean[tid] = g_gnm[b*NG+tid]; s_istd[tid] = g_gni[b*NG+tid]; }
    for (int i = tid; i < TILE; i += 256) {
        int yy = i / ROWW, xx = i - yy*ROWW;
        int gy = refl(y0 + yy - 1), gx = refl(x0 + xx - 1);
        s_inv[i] = g_invn[b*PP + gy*WW + gx];
    }
    __syncthreads();

    float dots[9];
    #pragma unroll
    for (int j = 0; j < 9; j++) dots[j] = 0.f;

    // pass 1: dot products
    for (int c0 = 0; c0 < CC; c0 += 8) {
        for (int i = tid; i < 8*TILE; i += 256) {
            int c = i / TILE, r = i - c*TILE;
            int yy = r / ROWW, xx = r - yy*ROWW;
            int gy = refl(y0 + yy - 1), gx = refl(x0 + xx - 1);
            s_t[c][r] = x[(size_t)((b*CC) + c0 + c) * PP + gy*WW + gx];
        }
        __syncthreads();
        #pragma unroll
        for (int cc = 0; cc < 8; cc++) {
            const float* t = s_t[cc];
            float v = t[(ty+1)*ROWW + tx + 1];
            #pragma unroll
            for (int dy = 0; dy < 3; dy++)
                #pragma unroll
                for (int dx = 0; dx < 3; dx++)
                    dots[dy*3+dx] += v * t[(ty+dy)*ROWW + tx + dx];
        }
        __syncthreads();
    }

    float invc = s_inv[(ty+1)*ROWW + tx + 1];
    float sims[9];
    #pragma unroll
    for (int j = 0; j < 9; j++) {
        int dy = j / 3, dx = j - dy*3;
        sims[j] = dots[j] * invc * s_inv[(ty+dy)*ROWW + tx + dx];
    }

    // connection count k from DF
    int p = (y0 + ty) * WW + x0 + tx;
    float df = g_df[b*PP + p];
    float mn = __uint_as_float(g_mm[2*b]);
    float mx = __uint_as_float(g_mm[2*b+1]);
    float dn = (df - mn) / (mx - mn + 1e-8f);
    int k = 1 + (int)rintf(dn * 7.f);
    if (k < 1) k = 1; if (k > 8) k = 8;

    // stable descending sort of (sim, idx) via 9-element network (registers only)
    float sv[9]; int si[9];
    #pragma unroll
    for (int j = 0; j < 9; j++) { sv[j] = sims[j]; si[j] = j; }
    CE(0,3); CE(1,7); CE(2,5); CE(4,8);
    CE(0,7); CE(2,4); CE(3,8); CE(5,6);
    CE(0,2); CE(1,3); CE(4,5); CE(7,8);
    CE(1,4); CE(3,6); CE(5,7);
    CE(0,1); CE(2,4); CE(3,5); CE(6,8);
    CE(2,3); CE(4,5); CE(6,7);
    CE(1,2); CE(3,4); CE(5,6);

    float ts = sv[0]; int tix = si[0];
    #pragma unroll
    for (int r = 0; r < 9; r++) { if (r == k-1) { ts = sv[r]; tix = si[r]; } }

    float wj[9]; float ws = 0.f;
    #pragma unroll
    for (int j = 0; j < 9; j++) {
        bool sel = (sims[j] > ts) || (sims[j] == ts && j <= tix);
        wj[j] = sel ? expf(sims[j]) : 0.f;
        ws += wj[j];
    }
    float iws = 1.f / ws;
    #pragma unroll
    for (int j = 0; j < 9; j++) wj[j] *= iws;

    // pass 2: weighted neighbor sum + groupnorm -> enhanced
    for (int c0 = 0; c0 < CC; c0 += 8) {
        for (int i = tid; i < 8*TILE; i += 256) {
            int c = i / TILE, r = i - c*TILE;
            int yy = r / ROWW, xx = r - yy*ROWW;
            int gy = refl(y0 + yy - 1), gx = refl(x0 + xx - 1);
            s_t[c][r] = x[(size_t)((b*CC) + c0 + c) * PP + gy*WW + gx];
        }
        __syncthreads();
        int g = c0 >> 3;
        float gm = s_mean[g], gi = s_istd[g];
        #pragma unroll
        for (int cc = 0; cc < 8; cc++) {
            const float* t = s_t[cc];
            float acc = 0.f;
            #pragma unroll
            for (int dy = 0; dy < 3; dy++)
                #pragma unroll
                for (int dx = 0; dx < 3; dx++)
                    acc += wj[dy*3+dx] * t[(ty+dy)*ROWW + tx + dx];
            float ctr = t[(ty+1)*ROWW + tx + 1];
            int c = c0 + cc;
            float gn = (ctr - gm) * gi * gnw[c] + gnb[c];
            g_enh[(size_t)(b*CC + c) * PP + p] = acc + gn;
        }
        __syncthreads();
    }
}

// ---------------- K5/K6: FFN GEMMs via TF32 tensor-core MMA ----------------
// CTA tile 128x128, 8 warps of 32(M)x64(N), K-chunks of 16 double-buffered.
// GEMM1 (SECOND=false): g_h = relu(w1[256x128] @ g_enh + b1)
// GEMM2 (SECOND=true):  out = g_enh + w2[128x256] @ g_h + b2

#define MMA_TF32(C, A, Bf) asm volatile( \
    "mma.sync.aligned.m16n8k8.row.col.f32.tf32.tf32.f32 " \
    "{%0,%1,%2,%3}, {%4,%5,%6,%7}, {%8,%9}, {%0,%1,%2,%3};\n" \
    : "+f"((C)[0]), "+f"((C)[1]), "+f"((C)[2]), "+f"((C)[3]) \
    : "r"((A)[0]), "r"((A)[1]), "r"((A)[2]), "r"((A)[3]), \
      "r"((Bf)[0]), "r"((Bf)[1]))

template<bool SECOND>
__global__ void __launch_bounds__(256) k_gemm(const float* __restrict__ W,
                                              const float* __restrict__ bias,
                                              float* __restrict__ OutExt) {
    constexpr int KTOT = SECOND ? 256 : 128;
    constexpr int MTOT = SECOND ? 128 : 256;
    constexpr int NCH  = KTOT / 16;

    const float* Bm = SECOND ? g_h : g_enh;
    float* Out      = SECOND ? OutExt : g_h;

    int bm = blockIdx.x, bn = blockIdx.y, b = blockIdx.z;
    const float* Bb = Bm + (size_t)b * KTOT * PP + bn*128;
    const float* Wb = W + bm*128*KTOT;

    __shared__ float As[2][128][20];   // [m][k], pad 20 -> conflict-free frags
    __shared__ float Bs[2][16][136];   // [k][n], pad 136

    int tid = threadIdx.x;
    int warp = tid >> 5, lane = tid & 31;
    int wm = (warp >> 1) * 32, wn = (warp & 1) * 64;
    int lm = lane >> 2, lk = lane & 3;

    float c[2][8][4];
    #pragma unroll
    for (int mt = 0; mt < 2; mt++)
        #pragma unroll
        for (int nt = 0; nt < 8; nt++)
            #pragma unroll
            for (int q = 0; q < 4; q++) c[mt][nt][q] = 0.f;

    float4 apre[2], bpre[2];

    // prologue: chunk 0
    {
        #pragma unroll
        for (int j = 0; j < 2; j++) {
            int ia = tid + 256*j;
            int m = ia >> 2, kq = ia & 3;
            apre[j] = *(const float4*)&Wb[m*KTOT + kq*4];
            int kk = ia >> 5, n4 = (ia & 31)*4;
            bpre[j] = *(const float4*)&Bb[(size_t)kk*PP + n4];
        }
        #pragma unroll
        for (int j = 0; j < 2; j++) {
            int ia = tid + 256*j;
            int m = ia >> 2, kq = ia & 3;
            float* d = &As[0][m][kq*4];
            d[0] = __uint_as_float(f2tf(apre[j].x));
            d[1] = __uint_as_float(f2tf(apre[j].y));
            d[2] = __uint_as_float(f2tf(apre[j].z));
            d[3] = __uint_as_float(f2tf(apre[j].w));
            int kk = ia >> 5, n4 = (ia & 31)*4;
            float* e = &Bs[0][kk][n4];
            e[0] = __uint_as_float(f2tf(bpre[j].x));
            e[1] = __uint_as_float(f2tf(bpre[j].y));
            e[2] = __uint_as_float(f2tf(bpre[j].z));
            e[3] = __uint_as_float(f2tf(bpre[j].w));
        }
    }
    __syncthreads();

    for (int ch = 0; ch < NCH; ch++) {
        int st = ch & 1;
        if (ch + 1 < NCH) {
            int k0 = (ch + 1) * 16;
            #pragma unroll
            for (int j = 0; j < 2; j++) {
                int ia = tid + 256*j;
                int m = ia >> 2, kq = ia & 3;
                apre[j] = *(const float4*)&Wb[m*KTOT + k0 + kq*4];
                int kk = ia >> 5, n4 = (ia & 31)*4;
                bpre[j] = *(const float4*)&Bb[(size_t)(k0 + kk)*PP + n4];
            }
        }
        // compute current chunk
        #pragma unroll
        for (int kc = 0; kc < 16; kc += 8) {
            unsigned a[2][4], bf[8][2];
            #pragma unroll
            for (int mt = 0; mt < 2; mt++) {
                int mr = wm + mt*16 + lm;
                a[mt][0] = __float_as_uint(As[st][mr    ][kc + lk]);
                a[mt][1] = __float_as_uint(As[st][mr + 8][kc + lk]);
                a[mt][2] = __float_as_uint(As[st][mr    ][kc + 4 + lk]);
                a[mt][3] = __float_as_uint(As[st][mr + 8][kc + 4 + lk]);
            }
            #pragma unroll
            for (int nt = 0; nt < 8; nt++) {
                int nc = wn + nt*8 + lm;
                bf[nt][0] = __float_as_uint(Bs[st][kc + lk    ][nc]);
                bf[nt][1] = __float_as_uint(Bs[st][kc + 4 + lk][nc]);
            }
            #pragma unroll
            for (int mt = 0; mt < 2; mt++)
                #pragma unroll
                for (int nt = 0; nt < 8; nt++)
                    MMA_TF32(c[mt][nt], a[mt], bf[nt]);
        }
        if (ch + 1 < NCH) {
            int so = st ^ 1;
            #pragma unroll
            for (int j = 0; j < 2; j++) {
                int ia = tid + 256*j;
                int m = ia >> 2, kq = ia & 3;
                float* d = &As[so][m][kq*4];
                d[0] = __uint_as_float(f2tf(apre[j].x));
                d[1] = __uint_as_float(f2tf(apre[j].y));
                d[2] = __uint_as_float(f2tf(apre[j].z));
                d[3] = __uint_as_float(f2tf(apre[j].w));
                int kk = ia >> 5, n4 = (ia & 31)*4;
                float* e = &Bs[so][kk][n4];
                e[0] = __uint_as_float(f2tf(bpre[j].x));
                e[1] = __uint_as_float(f2tf(bpre[j].y));
                e[2] = __uint_as_float(f2tf(bpre[j].z));
                e[3] = __uint_as_float(f2tf(bpre[j].w));
            }
        }
        __syncthreads();
    }

    // epilogue
    #pragma unroll
    for (int mt = 0; mt < 2; mt++) {
        int mr = bm*128 + wm + mt*16 + lm;
        float bi0 = bias[mr], bi1 = bias[mr + 8];
        #pragma unroll
        for (int nt = 0; nt < 8; nt++) {
            int col = bn*128 + wn + nt*8 + 2*lk;
            size_t o0 = (size_t)(b*MTOT + mr) * PP + col;
            size_t o1 = o0 + (size_t)8 * PP;
            float2 v0, v1;
            v0.x = c[mt][nt][0] + bi0; v0.y = c[mt][nt][1] + bi0;
            v1.x = c[mt][nt][2] + bi1; v1.y = c[mt][nt][3] + bi1;
            if (!SECOND) {
                v0.x = fmaxf(v0.x, 0.f); v0.y = fmaxf(v0.y, 0.f);
                v1.x = fmaxf(v1.x, 0.f); v1.y = fmaxf(v1.y, 0.f);
            } else {
                float2 r0 = *(const float2*)&g_enh[o0];
                float2 r1 = *(const float2*)&g_enh[o1];
                v0.x += r0.x; v0.y += r0.y;
                v1.x += r1.x; v1.y += r1.y;
            }
            *(float2*)&Out[o0] = v0;
            *(float2*)&Out[o1] = v1;
        }
    }
}

// ---------------- launch ----------------
extern "C" void kernel_launch(void* const* d_in, const int* in_sizes, int n_in,
                              void* d_out, int out_size) {
    const float* x   = (const float*)d_in[0];
    const float* gnw = (const float*)d_in[1];
    const float* gnb = (const float*)d_in[2];
    const float* w1  = (const float*)d_in[3];
    const float* b1  = (const float*)d_in[4];
    const float* w2  = (const float*)d_in[5];
    const float* b2  = (const float*)d_in[6];
    float* out = (float*)d_out;

    k_init <<<1, 256>>>();
    k_stats<<<BB*PP/256, 256>>>(x);
    k_df   <<<BB*PP/256, 256>>>();
    k_gn   <<<1, 128>>>();
    k_main <<<dim3(WW/TW, HH/TH, BB), dim3(TW, TH)>>>(x, gnw, gnb);
    k_gemm<false><<<dim3(2, PP/128, BB), 256>>>(w1, b1, nullptr);
    k_gemm<true> <<<dim3(1, PP/128, BB), 256>>>(w2, b2, out);
}

// round 4
// speedup vs baseline: 2.5960x; 1.3805x over previous
#include <cuda_runtime.h>
#include <cuda_bf16.h>
#include <math.h>

// Problem constants
#define BB 8
#define CC 128
#define HH 96
#define WW 96
#define PP (HH*WW)       // 9216
#define NG 16            // groups
#define CPG 8            // channels per group

// ---------------- scratch (device globals; no allocs allowed) ----------------
__device__ float g_avg [BB*PP];
__device__ float g_invn[BB*PP];
__device__ float g_df  [BB*PP];
__device__ unsigned g_mm[2*BB];
__device__ float g_gs  [BB*NG];
__device__ float g_gss [BB*NG];
__device__ float g_gnm [BB*NG];
__device__ float g_gni [BB*NG];
__device__ float g_enh [BB*CC*PP];         // enhanced (out + groupnorm)

__device__ __forceinline__ int refl(int i) {
    return i < 0 ? -i : (i >= HH ? 2*HH - 2 - i : i);
}

__device__ __forceinline__ unsigned packbf(float lo, float hi) {
    unsigned d;
    asm("cvt.rn.bf16x2.f32 %0, %1, %2;" : "=r"(d) : "f"(hi), "f"(lo));
    return d;
}

// ---------------- K0: reset accumulators ----------------
__global__ void k_init() {
    int t = threadIdx.x;
    if (t < BB*NG) { g_gs[t] = 0.f; g_gss[t] = 0.f; }
    if (t < BB) { g_mm[2*t] = 0x7F800000u; g_mm[2*t+1] = 0u; }
}

// ---------------- K1: per-pixel avg & inv-norm, per-(b,g) sums ----------------
__global__ void k_stats(const float* __restrict__ x) {
    int tid = threadIdx.x;
    int idx = blockIdx.x * 256 + tid;        // (b,p)
    int b = idx / PP;
    const float* xb = x + (size_t)b * CC * PP + (idx - b*PP);
    int lane = tid & 31;

    __shared__ float s_gs[NG], s_gss[NG];
    if (tid < NG) { s_gs[tid] = 0.f; s_gss[tid] = 0.f; }
    __syncthreads();

    float sum = 0.f, ssq = 0.f;
    #pragma unroll
    for (int g = 0; g < NG; g++) {
        float gs = 0.f, gss = 0.f;
        #pragma unroll
        for (int cc = 0; cc < CPG; cc++) {
            float v = xb[(size_t)(g*CPG + cc) * PP];
            gs += v; gss += v*v;
        }
        sum += gs; ssq += gss;
        #pragma unroll
        for (int off = 16; off; off >>= 1) {
            gs  += __shfl_xor_sync(0xffffffffu, gs,  off);
            gss += __shfl_xor_sync(0xffffffffu, gss, off);
        }
        if (lane == 0) { atomicAdd(&s_gs[g], gs); atomicAdd(&s_gss[g], gss); }
    }
    __syncthreads();
    if (tid < NG) {
        atomicAdd(&g_gs [b*NG + tid], s_gs [tid]);
        atomicAdd(&g_gss[b*NG + tid], s_gss[tid]);
    }
    g_avg [idx] = sum * (1.f/128.f);
    g_invn[idx] = 1.f / fmaxf(sqrtf(ssq), 1e-12f);
}

// ---------------- K2: laplacian of avg (zero pad), per-batch min/max ----------------
__global__ void k_df() {
    int tid = threadIdx.x;
    int idx = blockIdx.x * 256 + tid;
    int b = idx / PP;
    int p = idx - b*PP;
    int y = p / WW, xq = p - y*WW;
    float c = g_avg[idx];
    float up = (y > 0)      ? g_avg[idx - WW] : 0.f;
    float dn = (y < HH-1)   ? g_avg[idx + WW] : 0.f;
    float lf = (xq > 0)     ? g_avg[idx - 1]  : 0.f;
    float rt = (xq < WW-1)  ? g_avg[idx + 1]  : 0.f;
    float df = fabsf(4.f*c - up - dn - lf - rt);
    g_df[idx] = df;

    __shared__ float smn[256], smx[256];
    smn[tid] = df; smx[tid] = df;
    __syncthreads();
    for (int s = 128; s; s >>= 1) {
        if (tid < s) {
            smn[tid] = fminf(smn[tid], smn[tid+s]);
            smx[tid] = fmaxf(smx[tid], smx[tid+s]);
        }
        __syncthreads();
    }
    if (tid == 0) {
        atomicMin(&g_mm[2*b],   __float_as_uint(smn[0]));
        atomicMax(&g_mm[2*b+1], __float_as_uint(smx[0]));
    }
}

// ---------------- K3: finalize GN stats ----------------
__global__ void k_gn() {
    int i = threadIdx.x;
    if (i < BB*NG) {
        const float N = (float)(CPG * PP);
        float mean = g_gs[i] / N;
        float var = g_gss[i] / N - mean*mean;
        g_gnm[i] = mean;
        g_gni[i] = rsqrtf(var + 1e-5f);
    }
}

// ---------------- K4: IPG core, single load of all channels into smem --------
#define TW 32
#define TH 8
#define ROWW 34          // TW+2
#define TILE (10*ROWW)   // 340
#define CSTR 132         // channel stride (128+4): conflict-free LDS.128/STS.128

#define CE(a_,b_) do { \
    if ((sv[b_] > sv[a_]) || (sv[b_] == sv[a_] && si[b_] < si[a_])) { \
        float t_ = sv[a_]; sv[a_] = sv[b_]; sv[b_] = t_; \
        int u_ = si[a_]; si[a_] = si[b_]; si[b_] = u_; } \
} while (0)

__global__ void __launch_bounds__(256) k_main(const float* __restrict__ x,
                                              const float* __restrict__ gnw,
                                              const float* __restrict__ gnb) {
    extern __shared__ float s_t[];          // [TILE][CSTR] = 179520 B
    __shared__ float s_inv[TILE];
    __shared__ float s_mean[NG], s_istd[NG];

    int b = blockIdx.z;
    int x0 = blockIdx.x * TW, y0 = blockIdx.y * TH;
    int tx = threadIdx.x, ty = threadIdx.y;
    int tid = ty * TW + tx;

    if (tid < NG) { s_mean[tid] = g_gnm[b*NG+tid]; s_istd[tid] = g_gni[b*NG+tid]; }

    // reflected global offsets for this thread's fill positions
    int gp[2]; int nfill = 0;
    #pragma unroll
    for (int j = 0; j < 2; j++) {
        int i = tid + 256*j;
        if (i < TILE) {
            int yy = i / ROWW, xx = i - yy*ROWW;
            gp[j] = refl(y0 + yy - 1)*WW + refl(x0 + xx - 1);
            nfill = j + 1;
        }
    }
    #pragma unroll
    for (int j = 0; j < 2; j++) {
        int i = tid + 256*j;
        if (i < TILE) s_inv[i] = g_invn[b*PP + gp[j]];
    }

    // fill all 128 channels, 4 at a time -> float4 STS (conflict-free)
    for (int c0 = 0; c0 < CC; c0 += 4) {
        const float* xb = x + ((size_t)b*CC + c0) * PP;
        #pragma unroll
        for (int j = 0; j < 2; j++) {
            int i = tid + 256*j;
            if (i < TILE) {
                float4 v;
                v.x = xb[gp[j]];
                v.y = xb[PP   + gp[j]];
                v.z = xb[2*PP + gp[j]];
                v.w = xb[3*PP + gp[j]];
                *(float4*)&s_t[(size_t)i*CSTR + c0] = v;
            }
        }
    }
    __syncthreads();

    // pass 1: 9 dot products over channels (float4 vectorized)
    float dots[9];
    #pragma unroll
    for (int j = 0; j < 9; j++) dots[j] = 0.f;

    for (int c0 = 0; c0 < CC; c0 += 4) {
        float4 t9[9];
        #pragma unroll
        for (int dy = 0; dy < 3; dy++)
            #pragma unroll
            for (int dx = 0; dx < 3; dx++)
                t9[dy*3+dx] = *(float4*)&s_t[(size_t)((ty+dy)*ROWW + tx+dx)*CSTR + c0];
        float4 v = t9[4];
        #pragma unroll
        for (int j = 0; j < 9; j++)
            dots[j] += v.x*t9[j].x + v.y*t9[j].y + v.z*t9[j].z + v.w*t9[j].w;
    }

    float invc = s_inv[(ty+1)*ROWW + tx + 1];
    float sims[9];
    #pragma unroll
    for (int j = 0; j < 9; j++) {
        int dy = j / 3, dx = j - dy*3;
        sims[j] = dots[j] * invc * s_inv[(ty+dy)*ROWW + tx + dx];
    }

    // connection count k from DF
    int p = (y0 + ty) * WW + x0 + tx;
    float df = g_df[b*PP + p];
    float mn = __uint_as_float(g_mm[2*b]);
    float mx = __uint_as_float(g_mm[2*b+1]);
    float dn = (df - mn) / (mx - mn + 1e-8f);
    int k = 1 + (int)rintf(dn * 7.f);
    if (k < 1) k = 1; if (k > 8) k = 8;

    // stable descending sort (sim, idx) via register sorting network
    float sv[9]; int si[9];
    #pragma unroll
    for (int j = 0; j < 9; j++) { sv[j] = sims[j]; si[j] = j; }
    CE(0,3); CE(1,7); CE(2,5); CE(4,8);
    CE(0,7); CE(2,4); CE(3,8); CE(5,6);
    CE(0,2); CE(1,3); CE(4,5); CE(7,8);
    CE(1,4); CE(3,6); CE(5,7);
    CE(0,1); CE(2,4); CE(3,5); CE(6,8);
    CE(2,3); CE(4,5); CE(6,7);
    CE(1,2); CE(3,4); CE(5,6);

    float ts = sv[0]; int tix = si[0];
    #pragma unroll
    for (int r = 0; r < 9; r++) { if (r == k-1) { ts = sv[r]; tix = si[r]; } }

    float wj[9]; float ws = 0.f;
    #pragma unroll
    for (int j = 0; j < 9; j++) {
        bool sel = (sims[j] > ts) || (sims[j] == ts && j <= tix);
        wj[j] = sel ? expf(sims[j]) : 0.f;
        ws += wj[j];
    }
    float iws = 1.f / ws;
    #pragma unroll
    for (int j = 0; j < 9; j++) wj[j] *= iws;

    // pass 2: weighted neighbor sum + groupnorm -> enhanced (smem already filled)
    for (int c0 = 0; c0 < CC; c0 += 4) {
        float4 t9[9];
        #pragma unroll
        for (int dy = 0; dy < 3; dy++)
            #pragma unroll
            for (int dx = 0; dx < 3; dx++)
                t9[dy*3+dx] = *(float4*)&s_t[(size_t)((ty+dy)*ROWW + tx+dx)*CSTR + c0];
        float4 acc = make_float4(0.f, 0.f, 0.f, 0.f);
        #pragma unroll
        for (int j = 0; j < 9; j++) {
            acc.x += wj[j]*t9[j].x; acc.y += wj[j]*t9[j].y;
            acc.z += wj[j]*t9[j].z; acc.w += wj[j]*t9[j].w;
        }
        float4 ctr = t9[4];
        int g = c0 >> 3;
        float gm = s_mean[g], gi = s_istd[g];
        float* dst = &g_enh[(size_t)(b*CC + c0) * PP + p];
        dst[0]     = acc.x + (ctr.x - gm)*gi*gnw[c0]   + gnb[c0];
        dst[PP]    = acc.y + (ctr.y - gm)*gi*gnw[c0+1] + gnb[c0+1];
        dst[2*PP]  = acc.z + (ctr.z - gm)*gi*gnw[c0+2] + gnb[c0+2];
        dst[3*PP]  = acc.w + (ctr.w - gm)*gi*gnw[c0+3] + gnb[c0+3];
    }
}

// ---------------- K5: fused FFN (bf16 mma, H kept in smem) ----------------
// Per CTA: 128-pixel column tile, batch b.
//   H  = relu(W1[256x128] @ E[:,tile] + b1)      (H in smem, bf16)
//   out = E + W2[128x256] @ H + b2
#define NT 128
#define ESTR 68      // words per n-row of Es (K=128 -> 64 words + 4 pad)
#define HSTR 132     // words per n-row of Hs (K=256 -> 128 words + 4 pad)
#define ASTR 20      // words per m-row of Aw chunk (k32 -> 16 words + 4 pad)

#define MMA_BF16(C, A, B2) asm volatile( \
    "mma.sync.aligned.m16n8k16.row.col.f32.bf16.bf16.f32 " \
    "{%0,%1,%2,%3}, {%4,%5,%6,%7}, {%8,%9}, {%0,%1,%2,%3};\n" \
    : "+f"((C)[0]), "+f"((C)[1]), "+f"((C)[2]), "+f"((C)[3]) \
    : "r"((A)[0]), "r"((A)[1]), "r"((A)[2]), "r"((A)[3]), \
      "r"((B2)[0]), "r"((B2)[1]))

__global__ void __launch_bounds__(512, 1) k_ffn(const float* __restrict__ w1,
                                                const float* __restrict__ b1,
                                                const float* __restrict__ w2,
                                                const float* __restrict__ b2,
                                                float* __restrict__ out) {
    extern __shared__ unsigned smu[];
    unsigned* Es = smu;                     // [128][ESTR]
    unsigned* Hs = Es + 128*ESTR;           // [128][HSTR]
    unsigned* Aw = Hs + 128*HSTR;           // [2][256][ASTR]

    int b = blockIdx.y;
    int n0 = blockIdx.x * NT;
    int tid = threadIdx.x;
    int warp = tid >> 5, lane = tid & 31;
    int lm = lane >> 2, lk = lane & 3;

    const float* E = g_enh + (size_t)b * CC * PP + n0;

    // ---- Es fill: E[k][n] fp32 -> bf16x2 pairs along k, n-major layout ----
    #pragma unroll
    for (int j = 0; j < 16; j++) {
        int i = tid + 512*j;
        int w = i >> 7, n = i & 127;
        float lo = E[(size_t)(2*w)   * PP + n];
        float hi = E[(size_t)(2*w+1) * PP + n];
        Es[n*ESTR + w] = packbf(lo, hi);
    }

    // ---- GEMM1: warp tile 32(M) x 64(N); 8 warp-rows x 2 warp-cols ----
    int wm1 = (warp >> 1) * 32, wn1 = (warp & 1) * 64;
    float c1[2][8][4];
    #pragma unroll
    for (int mt = 0; mt < 2; mt++)
        #pragma unroll
        for (int nt = 0; nt < 8; nt++)
            #pragma unroll
            for (int q = 0; q < 4; q++) c1[mt][nt][q] = 0.f;

    float2 av[8];
    // prologue: W1 chunk 0 (k 0..31)
    #pragma unroll
    for (int j = 0; j < 8; j++) {
        int i = tid + 512*j; int m = i >> 4, w = i & 15;
        av[j] = *(const float2*)&w1[m*128 + 2*w];
    }
    #pragma unroll
    for (int j = 0; j < 8; j++) {
        int i = tid + 512*j; int m = i >> 4, w = i & 15;
        Aw[m*ASTR + w] = packbf(av[j].x, av[j].y);
    }
    __syncthreads();

    for (int ch = 0; ch < 4; ch++) {
        if (ch < 3) {
            int k0n = (ch + 1) * 32;
            #pragma unroll
            for (int j = 0; j < 8; j++) {
                int i = tid + 512*j; int m = i >> 4, w = i & 15;
                av[j] = *(const float2*)&w1[m*128 + k0n + 2*w];
            }
        }
        unsigned* A = Aw + (ch & 1) * 256 * ASTR;
        #pragma unroll
        for (int ks = 0; ks < 2; ks++) {
            int kw = ch*16 + ks*8;               // global word base in Es
            unsigned a[2][4], bw[8][2];
            #pragma unroll
            for (int mt = 0; mt < 2; mt++) {
                int mr = wm1 + mt*16 + lm;
                a[mt][0] = A[mr*ASTR     + ks*8 + lk];
                a[mt][1] = A[(mr+8)*ASTR + ks*8 + lk];
                a[mt][2] = A[mr*ASTR     + ks*8 + 4 + lk];
                a[mt][3] = A[(mr+8)*ASTR + ks*8 + 4 + lk];
            }
            #pragma unroll
            for (int nt = 0; nt < 8; nt++) {
                int nc = wn1 + nt*8 + lm;
                bw[nt][0] = Es[nc*ESTR + kw + lk];
                bw[nt][1] = Es[nc*ESTR + kw + 4 + lk];
            }
            #pragma unroll
            for (int mt = 0; mt < 2; mt++)
                #pragma unroll
                for (int nt = 0; nt < 8; nt++)
                    MMA_BF16(c1[mt][nt], a[mt], bw[nt]);
        }
        if (ch < 3) {
            unsigned* A2 = Aw + ((ch + 1) & 1) * 256 * ASTR;
            #pragma unroll
            for (int j = 0; j < 8; j++) {
                int i = tid + 512*j; int m = i >> 4, w = i & 15;
                A2[m*ASTR + w] = packbf(av[j].x, av[j].y);
            }
        }
        __syncthreads();
    }

    // ---- H: bias + relu, pack row pairs via shfl, store n-major bf16 ----
    #pragma unroll
    for (int mt = 0; mt < 2; mt++) {
        int mr = wm1 + mt*16 + lm;
        float bi0 = b1[mr], bi1 = b1[mr + 8];
        #pragma unroll
        for (int nt = 0; nt < 8; nt++) {
            float v0 = fmaxf(c1[mt][nt][0] + bi0, 0.f);
            float v1 = fmaxf(c1[mt][nt][1] + bi0, 0.f);
            float v2 = fmaxf(c1[mt][nt][2] + bi1, 0.f);
            float v3 = fmaxf(c1[mt][nt][3] + bi1, 0.f);
            float p0 = __shfl_xor_sync(0xffffffffu, v0, 4);
            float p1 = __shfl_xor_sync(0xffffffffu, v1, 4);
            float p2 = __shfl_xor_sync(0xffffffffu, v2, 4);
            float p3 = __shfl_xor_sync(0xffffffffu, v3, 4);
            if (!(lm & 1)) {                      // even rows pack (mr, mr+1)
                int colA = wn1 + nt*8 + 2*lk;
                int w0 = mr >> 1;
                Hs[colA    *HSTR + w0]     = packbf(v0, p0);
                Hs[(colA+1)*HSTR + w0]     = packbf(v1, p1);
                Hs[colA    *HSTR + w0 + 4] = packbf(v2, p2);
                Hs[(colA+1)*HSTR + w0 + 4] = packbf(v3, p3);
            }
        }
    }
    __syncthreads();

    // ---- GEMM2: warp tile 32(M) x 32(N); 4 warp-rows x 4 warp-cols ----
    int wm2 = (warp >> 2) * 32, wn2 = (warp & 3) * 32;
    float c2[2][4][4];
    #pragma unroll
    for (int mt = 0; mt < 2; mt++)
        #pragma unroll
        for (int nt = 0; nt < 4; nt++)
            #pragma unroll
            for (int q = 0; q < 4; q++) c2[mt][nt][q] = 0.f;

    float2 av2[4];
    // prologue: W2 chunk 0
    #pragma unroll
    for (int j = 0; j < 4; j++) {
        int i = tid + 512*j; int m = i >> 4, w = i & 15;
        av2[j] = *(const float2*)&w2[m*256 + 2*w];
    }
    #pragma unroll
    for (int j = 0; j < 4; j++) {
        int i = tid + 512*j; int m = i >> 4, w = i & 15;
        Aw[m*ASTR + w] = packbf(av2[j].x, av2[j].y);
    }
    __syncthreads();

    for (int ch = 0; ch < 8; ch++) {
        if (ch < 7) {
            int k0n = (ch + 1) * 32;
            #pragma unroll
            for (int j = 0; j < 4; j++) {
                int i = tid + 512*j; int m = i >> 4, w = i & 15;
                av2[j] = *(const float2*)&w2[m*256 + k0n + 2*w];
            }
        }
        unsigned* A = Aw + (ch & 1) * 256 * ASTR;
        #pragma unroll
        for (int ks = 0; ks < 2; ks++) {
            int kw = ch*16 + ks*8;               // global word base in Hs
            unsigned a[2][4], bw[4][2];
            #pragma unroll
            for (int mt = 0; mt < 2; mt++) {
                int mr = wm2 + mt*16 + lm;
                a[mt][0] = A[mr*ASTR     + ks*8 + lk];
                a[mt][1] = A[(mr+8)*ASTR + ks*8 + lk];
                a[mt][2] = A[mr*ASTR     + ks*8 + 4 + lk];
                a[mt][3] = A[(mr+8)*ASTR + ks*8 + 4 + lk];
            }
            #pragma unroll
            for (int nt = 0; nt < 4; nt++) {
                int nc = wn2 + nt*8 + lm;
                bw[nt][0] = Hs[nc*HSTR + kw + lk];
                bw[nt][1] = Hs[nc*HSTR + kw + 4 + lk];
            }
            #pragma unroll
            for (int mt = 0; mt < 2; mt++)
                #pragma unroll
                for (int nt = 0; nt < 4; nt++)
                    MMA_BF16(c2[mt][nt], a[mt], bw[nt]);
        }
        if (ch < 7) {
            unsigned* A2 = Aw + ((ch + 1) & 1) * 256 * ASTR;
            #pragma unroll
            for (int j = 0; j < 4; j++) {
                int i = tid + 512*j; int m = i >> 4, w = i & 15;
                A2[m*ASTR + w] = packbf(av2[j].x, av2[j].y);
            }
        }
        __syncthreads();
    }

    // ---- epilogue: out = enhanced + ffn + b2 ----
    #pragma unroll
    for (int mt = 0; mt < 2; mt++) {
        int mr = wm2 + mt*16 + lm;
        float bi0 = b2[mr], bi1 = b2[mr + 8];
        #pragma unroll
        for (int nt = 0; nt < 4; nt++) {
            int col = wn2 + nt*8 + 2*lk;
            size_t o0 = (size_t)(b*CC + mr) * PP + n0 + col;
            size_t o1 = o0 + (size_t)8 * PP;
            float2 e0 = *(const float2*)&g_enh[o0];
            float2 e1 = *(const float2*)&g_enh[o1];
            float2 v0, v1;
            v0.x = c2[mt][nt][0] + bi0 + e0.x;
            v0.y = c2[mt][nt][1] + bi0 + e0.y;
            v1.x = c2[mt][nt][2] + bi1 + e1.x;
            v1.y = c2[mt][nt][3] + bi1 + e1.y;
            *(float2*)&out[o0] = v0;
            *(float2*)&out[o1] = v1;
        }
    }
}

// ---------------- launch ----------------
extern "C" void kernel_launch(void* const* d_in, const int* in_sizes, int n_in,
                              void* d_out, int out_size) {
    const float* x   = (const float*)d_in[0];
    const float* gnw = (const float*)d_in[1];
    const float* gnb = (const float*)d_in[2];
    const float* w1  = (const float*)d_in[3];
    const float* b1  = (const float*)d_in[4];
    const float* w2  = (const float*)d_in[5];
    const float* b2  = (const float*)d_in[6];
    float* out = (float*)d_out;

    const int smem_main = TILE * CSTR * 4;                         // 179520 B
    const int smem_ffn  = (128*ESTR + 128*HSTR + 2*256*ASTR) * 4;  // 143360 B
    cudaFuncSetAttribute(k_main, cudaFuncAttributeMaxDynamicSharedMemorySize, smem_main);
    cudaFuncSetAttribute(k_ffn,  cudaFuncAttributeMaxDynamicSharedMemorySize, smem_ffn);

    k_init <<<1, 256>>>();
    k_stats<<<BB*PP/256, 256>>>(x);
    k_df   <<<BB*PP/256, 256>>>();
    k_gn   <<<1, 128>>>();
    k_main <<<dim3(WW/TW, HH/TH, BB), dim3(TW, TH), smem_main>>>(x, gnw, gnb);
    k_ffn  <<<dim3(PP/NT, BB), 512, smem_ffn>>>(w1, b1, w2, b2, out);
}